// round 9
// baseline (speedup 1.0000x reference)
#include <cuda_runtime.h>
#include <math.h>
#include <stdint.h>

// ---------------------------------------------------------------------------
// VQ-VAE VectorQuantizer forward — exact fp32 f32x2 engine, K-split x4 for
// wave balance (1024 CTAs, u64 atomicMin merge), cp.async staged codebook.
//   out = [ z_q_st (2097152) | vq_loss | indices (32768) | perplexity | usage (1024) ]
// ---------------------------------------------------------------------------

#define D_DIM   64
#define KCODES  1024
#define HW      1024
#define TM      128          // pixels per tile
#define KC      128          // codes per chunk
#define NPT     256          // pixel tiles
#define KSPLIT  4            // code-range split (256 codes per CTA)

#define OFS_LOSS  2097152
#define OFS_IDX   2097153
#define OFS_PPL   2129921
#define OFS_USAGE 2129922

__device__ int                g_counts[KCODES];
__device__ float              g_e2[KCODES];
__device__ float              g_sse;
__device__ int                g_done[NPT];
__device__ unsigned long long g_best[NPT * TM];
__device__ __align__(16) float g_eT[D_DIM * KCODES];   // codebook transposed [d][k]

// ---- packed f32x2 helpers --------------------------------------------------
__device__ __forceinline__ unsigned long long pack2(float x, float y) {
    unsigned long long r;
    asm("mov.b64 %0, {%1, %2};" : "=l"(r) : "f"(x), "f"(y));
    return r;
}
__device__ __forceinline__ void fma2(unsigned long long& d,
                                     unsigned long long a,
                                     unsigned long long b) {
    asm("fma.rn.f32x2 %0, %1, %2, %0;" : "+l"(d) : "l"(a), "l"(b));
}
__device__ __forceinline__ float2 unpack2(unsigned long long v) {
    float2 f;
    asm("mov.b64 {%0, %1}, %2;" : "=f"(f.x), "=f"(f.y) : "l"(v));
    return f;
}
__device__ __forceinline__ uint32_t smem_u32(const void* p) {
    uint32_t a;
    asm("{ .reg .u64 t; cvta.to.shared.u64 t, %1; cvt.u32.u64 %0, t; }"
        : "=r"(a) : "l"(p));
    return a;
}
__device__ __forceinline__ void cp_async16(uint32_t dst, const void* src) {
    asm volatile("cp.async.cg.shared.global [%0], [%1], 16;"
                 :: "r"(dst), "l"(src) : "memory");
}
#define CP_COMMIT()  asm volatile("cp.async.commit_group;" ::: "memory")
#define CP_WAIT(n)   asm volatile("cp.async.wait_group %0;" :: "n"(n) : "memory")

// ---- smem layout (float offsets) -------------------------------------------
#define Z_OFF     0          // z_s [64][132]            8448 f
#define EB0_OFF   8448       // ebuf0 [64][128]          8192 f (aliased post-MMA)
#define EB1_OFF   16640      // ebuf1 [64][128]          8192 f (zq stage aliases)
#define E2_OFF    24832      // e2s [256]                 256 f
#define Z2_OFF    25088      // z2_s [128]                128 f
#define FLAG_OFF  25216      // ticket flag                 1
#define SMEM_F    25220
#define SMEM_BYTES (SMEM_F * 4)
// aliases inside EB0 (dead after compute):
//   red_d = EB0+0 (1024f)  red_i = EB0+1024  idx = EB0+2048 (128)  hist = EB0+3072 (1024)
// zq stage = EB1 with pitch 132 (spills 256f into E2 region — dead by then)

// ---------------------------------------------------------------------------
// Kernel 1: prep — e2 (reference rounding), transposed codebook, merge-state init
// ---------------------------------------------------------------------------
__global__ void vq_prep(const float* __restrict__ cb) {
    const int tidg = blockIdx.x * 256 + threadIdx.x;    // grid 32 x 256 = 8192
    if (tidg < KCODES) {
        const int k = tidg;
        const float4* row = reinterpret_cast<const float4*>(cb + (size_t)k * D_DIM);
        float v[D_DIM];
        float s = 0.f;
#pragma unroll
        for (int q = 0; q < 16; ++q) {
            float4 x = row[q];
            v[4 * q + 0] = x.x; v[4 * q + 1] = x.y;
            v[4 * q + 2] = x.z; v[4 * q + 3] = x.w;
        }
#pragma unroll
        for (int d = 0; d < D_DIM; ++d) s = fmaf(v[d], v[d], s);   // d-ascending
        g_e2[k] = s;
#pragma unroll
        for (int d = 0; d < D_DIM; ++d) g_eT[d * KCODES + k] = v[d];
        g_counts[k] = 0;
    }
#pragma unroll
    for (int i = 0; i < 4; ++i)
        g_best[tidg * 4 + i] = (0x7F800000ull << 32) | 0xFFFFFFFFull;  // +inf, max k
    if (tidg < NPT) g_done[tidg] = 0;
    if (tidg == 0)  g_sse = 0.f;
}

// ---------------------------------------------------------------------------
// chunk compute: 64 d-iters, 8 px x 8 codes per thread (identical math to R8)
// ---------------------------------------------------------------------------
__device__ __forceinline__ void compute_chunk(
    const float* __restrict__ SM, const float* __restrict__ eb,
    int kglob0, int kloc_e2, int p0, int kloc0,
    const float* z2r, const float* e2s,
    float* bestd, int* besti) {

    unsigned long long acc[8][4];
#pragma unroll
    for (int j = 0; j < 8; ++j)
#pragma unroll
        for (int kk = 0; kk < 4; ++kk) acc[j][kk] = 0ull;

#pragma unroll 16
    for (int d = 0; d < D_DIM; ++d) {
        ulonglong2 eA = *reinterpret_cast<const ulonglong2*>(&eb[d * KC + kloc0]);
        ulonglong2 eB = *reinterpret_cast<const ulonglong2*>(&eb[d * KC + kloc0 + 4]);
        float4 za = *reinterpret_cast<const float4*>(&SM[Z_OFF + d * 132 + p0]);
        float4 zb = *reinterpret_cast<const float4*>(&SM[Z_OFF + d * 132 + p0 + 4]);
        float zr[8] = {za.x, za.y, za.z, za.w, zb.x, zb.y, zb.z, zb.w};
#pragma unroll
        for (int j = 0; j < 8; ++j) {
            unsigned long long zz = pack2(zr[j], zr[j]);
            fma2(acc[j][0], zz, eA.x);
            fma2(acc[j][1], zz, eA.y);
            fma2(acc[j][2], zz, eB.x);
            fma2(acc[j][3], zz, eB.y);
        }
    }

    float e2r[8];
#pragma unroll
    for (int kk = 0; kk < 8; ++kk) e2r[kk] = e2s[kloc_e2 + kloc0 + kk];

#pragma unroll
    for (int j = 0; j < 8; ++j) {
        float a = z2r[j];
#pragma unroll
        for (int kk = 0; kk < 4; ++kk) {
            float2 s = unpack2(acc[j][kk]);
            float d0 = fmaf(-2.f, s.x, a + e2r[kk * 2]);
            float d1 = fmaf(-2.f, s.y, a + e2r[kk * 2 + 1]);
            int k0 = kglob0 + kloc0 + kk * 2;
            if (d0 < bestd[j]) { bestd[j] = d0; besti[j] = k0; }
            if (d1 < bestd[j]) { bestd[j] = d1; besti[j] = k0 + 1; }
        }
    }
}

// ---------------------------------------------------------------------------
// Kernel 2: main — grid 1024: CTA = (pixel-tile, code-quarter)
// ---------------------------------------------------------------------------
__global__ void __launch_bounds__(256, 2)
vq_main(const float* __restrict__ ze, const float* __restrict__ cb,
        float* __restrict__ out) {
    extern __shared__ __align__(16) float SM[];

    const int tid   = threadIdx.x;
    const int q     = blockIdx.x & 3;          // code quarter
    const int tile  = blockIdx.x >> 2;         // pixel tile
    const int qbase = q * 256;
    const int b     = tile >> 3;
    const int hw0   = (tile & 7) * TM;
    const float* zbase = ze + (size_t)b * D_DIM * HW + hw0;

    float* EB0  = SM + EB0_OFF;
    float* EB1  = SM + EB1_OFF;
    float* e2s  = SM + E2_OFF;
    float* z2_s = SM + Z2_OFF;
    int*   flag = reinterpret_cast<int*>(SM + FLAG_OFF);

    // ---- stage both code chunks via cp.async (overlaps z load) ------------
    {
        const int d_st = tid >> 2, q_st = tid & 3;           // 128B per thread
        const float* s0 = g_eT + d_st * KCODES + qbase + q_st * 32;
        uint32_t dA = smem_u32(EB0 + d_st * KC + q_st * 32);
#pragma unroll
        for (int i = 0; i < 8; ++i) cp_async16(dA + i * 16, s0 + i * 4);
        CP_COMMIT();
        const float* s1 = s0 + KC;
        uint32_t dB = smem_u32(EB1 + d_st * KC + q_st * 32);
#pragma unroll
        for (int i = 0; i < 8; ++i) cp_async16(dB + i * 16, s1 + i * 4);
        CP_COMMIT();
    }

    // ---- z tile + e2 slice -------------------------------------------------
    for (int f = tid; f < D_DIM * TM; f += 256) {
        int d = f >> 7, p = f & 127;
        SM[Z_OFF + d * 132 + p] = zbase[d * HW + p];
    }
    e2s[tid] = g_e2[qbase + tid];
    __syncthreads();

    if (tid < TM) {                                          // reference rounding
        float s = 0.f;
#pragma unroll
        for (int d = 0; d < D_DIM; ++d) {
            float v = SM[Z_OFF + d * 132 + tid];
            s = fmaf(v, v, s);
        }
        z2_s[tid] = s;
    }
    __syncthreads();

    const int pcol  = tid & 15;
    const int krow  = tid >> 4;
    const int p0    = pcol * 8;
    const int kloc0 = krow * 8;

    float z2r[8];
#pragma unroll
    for (int j = 0; j < 8; ++j) z2r[j] = z2_s[p0 + j];

    float bestd[8];
    int   besti[8];
#pragma unroll
    for (int j = 0; j < 8; ++j) { bestd[j] = 3.4e38f; besti[j] = 0; }

    CP_WAIT(1); __syncthreads();                             // chunk 0 landed
    compute_chunk(SM, EB0, qbase, 0, p0, kloc0, z2r, e2s, bestd, besti);
    CP_WAIT(0); __syncthreads();                             // chunk 1 landed
    compute_chunk(SM, EB1, qbase + KC, KC, p0, kloc0, z2r, e2s, bestd, besti);

    // ---- cross-thread argmin (identical structure to R8) -------------------
#pragma unroll
    for (int j = 0; j < 8; ++j) {
        float od = __shfl_xor_sync(0xffffffffu, bestd[j], 16);
        int   oi = __shfl_xor_sync(0xffffffffu, besti[j], 16);
        if (od < bestd[j] || (od == bestd[j] && oi < besti[j])) {
            bestd[j] = od; besti[j] = oi;
        }
    }
    float* red_d = EB0;                                      // aliases (compute done)
    int*   red_i = reinterpret_cast<int*>(EB0 + 1024);
    int*   idx_s = reinterpret_cast<int*>(EB0 + 2048);
    int*   hist  = reinterpret_cast<int*>(EB0 + 3072);
    const int w = tid >> 5;
    if ((tid & 16) == 0) {
#pragma unroll
        for (int j = 0; j < 8; ++j) {
            red_d[w * TM + p0 + j] = bestd[j];
            red_i[w * TM + p0 + j] = besti[j];
        }
    }
    __syncthreads();

    if (tid < TM) {
        float bd = red_d[tid];
        int   bi = red_i[tid];
#pragma unroll
        for (int w2 = 1; w2 < 8; ++w2) {
            float d2 = red_d[w2 * TM + tid];
            int   i2 = red_i[w2 * TM + tid];
            if (d2 < bd || (d2 == bd && i2 < bi)) { bd = d2; bi = i2; }
        }
        // dist > 0 always (z2 >> 2*max|dot|) -> float bits order-preserving
        unsigned long long pk = ((unsigned long long)__float_as_uint(bd) << 32)
                              | (unsigned)bi;
        atomicMin(&g_best[tile * TM + tid], pk);
    }
    __threadfence();
    if (tid == 0) *flag = (atomicAdd(&g_done[tile], 1) == KSPLIT - 1) ? 1 : 0;
    __syncthreads();
    if (!*flag) return;

    // ======================= last CTA: epilogue ============================
    __threadfence();
    for (int i = tid; i < KCODES; i += 256) hist[i] = 0;
    __syncthreads();

    if (tid < TM) {
        unsigned long long v =
            *reinterpret_cast<volatile unsigned long long*>(&g_best[tile * TM + tid]);
        int bi = (int)(unsigned)(v & 0xFFFFFFFFull);
        idx_s[tid] = bi;
        out[OFS_IDX + tile * TM + tid] = (float)bi;
        atomicAdd(&hist[bi], 1);
    }
    __syncthreads();

    for (int i = tid; i < KCODES; i += 256) {
        int cnum = hist[i];
        if (cnum) atomicAdd(&g_counts[i], cnum);
    }

    // gather z_q, z_q_st with reference's two roundings, SSE; stage at EB1
    {
        int p = tid >> 1, h = tid & 1;
        int ci = idx_s[p];
        const float4* crow = reinterpret_cast<const float4*>(
                                 cb + (size_t)ci * D_DIM) + h * 8;
        float ssel = 0.f;
#pragma unroll
        for (int i = 0; i < 8; ++i) {
            float4 v = crow[i];
            int d0 = h * 32 + i * 4;
            float vv[4] = {v.x, v.y, v.z, v.w};
#pragma unroll
            for (int cc = 0; cc < 4; ++cc) {
                int d = d0 + cc;
                float zev  = SM[Z_OFF + d * 132 + p];
                float diff = vv[cc] - zev;           // fl(z_q - z_e)
                ssel = fmaf(diff, diff, ssel);
                EB1[d * 132 + p] = zev + diff;       // fl(z_e + fl(z_q - z_e))
            }
        }
#pragma unroll
        for (int o = 16; o; o >>= 1) ssel += __shfl_xor_sync(0xffffffffu, ssel, o);
        if ((tid & 31) == 0) atomicAdd(&g_sse, ssel);
    }
    __syncthreads();

    float* zo = out + (size_t)b * D_DIM * HW + hw0;
    for (int f = tid; f < D_DIM * TM; f += 256) {
        int d = f >> 7, p = f & 127;
        zo[d * HW + p] = EB1[d * 132 + p];
    }
}

// ---------------------------------------------------------------------------
// Kernel 3: finalize — usage, perplexity, vq_loss
// ---------------------------------------------------------------------------
__global__ void vq_final(float* __restrict__ out) {
    __shared__ float red[32];
    int t = threadIdx.x;
    float u = (float)g_counts[t] / 32768.0f;
    out[OFS_USAGE + t] = u;
    float h = u * logf(u + 1e-10f);
#pragma unroll
    for (int o = 16; o; o >>= 1) h += __shfl_xor_sync(0xffffffffu, h, o);
    if ((t & 31) == 0) red[t >> 5] = h;
    __syncthreads();
    if (t < 32) {
        float v = red[t];
#pragma unroll
        for (int o = 16; o; o >>= 1) v += __shfl_xor_sync(0xffffffffu, v, o);
        if (t == 0) {
            out[OFS_PPL] = expf(-v);
            float m = g_sse / 2097152.0f;
            out[OFS_LOSS] = m + 0.25f * m;
        }
    }
}

// ---------------------------------------------------------------------------
extern "C" void kernel_launch(void* const* d_in, const int* in_sizes, int n_in,
                              void* d_out, int out_size) {
    const float* a0 = (const float*)d_in[0];
    const float* a1 = (const float*)d_in[1];
    const float* ze = a0;
    const float* cb = a1;
    if (n_in >= 2 && in_sizes[0] == KCODES * D_DIM) { ze = a1; cb = a0; }
    float* out = (float*)d_out;

    cudaFuncSetAttribute(vq_main, cudaFuncAttributeMaxDynamicSharedMemorySize,
                         SMEM_BYTES);

    vq_prep<<<32, 256>>>(cb);
    vq_main<<<NPT * KSPLIT, 256, SMEM_BYTES>>>(ze, cb, out);
    vq_final<<<1, 1024>>>(out);
}

// round 10
// speedup vs baseline: 1.0194x; 1.0194x over previous
#include <cuda_runtime.h>
#include <math.h>
#include <stdint.h>

// ---------------------------------------------------------------------------
// VQ-VAE VectorQuantizer forward — single persistent kernel.
//  * exact fp32 f32x2 FMA engine (byte-identical math to the 126us R8 kernel)
//  * 296 CTAs (2/SM), 2048 (tile,chunk) quanta statically split -> 1.2% imbalance
//  * per-tile merge via atomicMax(~packed) ; zero-initialized global = identity
//  * 8th-chunk finisher runs tile epilogue; 256th-tile finisher runs finalize
//    and resets module state (graph-replay safe)
//   out = [ z_q_st (2097152) | vq_loss | indices (32768) | perplexity | usage (1024) ]
// ---------------------------------------------------------------------------

#define D_DIM   64
#define KCODES  1024
#define HW      1024
#define TM      128
#define KC      128
#define NPT     256                 // pixel tiles
#define QTOT    2048                // 256 tiles x 8 chunks
#define NCTA    296                 // 2 per SM on 148 SMs

#define OFS_LOSS  2097152
#define OFS_IDX   2097153
#define OFS_PPL   2129921
#define OFS_USAGE 2129922

__device__ int                g_counts[KCODES];      // zero-init; reset by finisher
__device__ float              g_sse;
__device__ int                g_done[NPT];
__device__ int                g_tiles_done;
__device__ unsigned long long g_best[NPT * TM];      // stores ~((dist_bits<<32)|k); 0 = identity

// ---- packed f32x2 helpers --------------------------------------------------
__device__ __forceinline__ unsigned long long pack2(float x, float y) {
    unsigned long long r;
    asm("mov.b64 %0, {%1, %2};" : "=l"(r) : "f"(x), "f"(y));
    return r;
}
__device__ __forceinline__ void fma2(unsigned long long& d,
                                     unsigned long long a,
                                     unsigned long long b) {
    asm("fma.rn.f32x2 %0, %1, %2, %0;" : "+l"(d) : "l"(a), "l"(b));
}
__device__ __forceinline__ float2 unpack2(unsigned long long v) {
    float2 f;
    asm("mov.b64 {%0, %1}, %2;" : "=f"(f.x), "=f"(f.y) : "l"(v));
    return f;
}

struct Sm {
    float z_s[D_DIM][TM + 4];     // 33792 B : z tile [d][p]
    float e_s[D_DIM][KC + 4];     // 33792 B : chunk [d][k]; zq stage aliases
    float e2c[KC];                //   512 B : current chunk e2
    float z2_s[TM];               //   512 B
    float red_d[8][TM];           //  4096 B
    int   red_i[8][TM];           //  4096 B
    int   idx_s[TM];              //   512 B
    int   cnt_s[KCODES];          //  4096 B
    int   flag, flag2;
};                                 // ~81.4 KB -> 2 CTAs/SM

__global__ void __launch_bounds__(256, 2)
vq_all(const float* __restrict__ ze, const float* __restrict__ cb,
       float* __restrict__ out) {
    extern __shared__ __align__(16) char smem_raw[];
    Sm* sm = reinterpret_cast<Sm*>(smem_raw);

    const int tid = threadIdx.x;
    const int q0  = (blockIdx.x * QTOT) / NCTA;
    const int q1  = ((blockIdx.x + 1) * QTOT) / NCTA;

    const int pcol  = tid & 15;
    const int krow  = tid >> 4;
    const int p0    = pcol * 8;
    const int kloc0 = krow * 8;
    const int k_st  = tid & 127;         // staging: warp-per-d-row, conflict-free
    const int h_st  = tid >> 7;

    int   cur_tile = -1, seg_chunks = 0, b = 0, hw0 = 0;
    float z2r[8];
    float bestd[8];
    int   besti[8];

    for (int q = q0;; ++q) {
        const int tile = (q < q1) ? (q >> 3) : -1;

        if (tile != cur_tile) {
            if (cur_tile >= 0) {
                // ============ segment flush: merge bests into g_best =========
#pragma unroll
                for (int j = 0; j < 8; ++j) {
                    float od = __shfl_xor_sync(0xffffffffu, bestd[j], 16);
                    int   oi = __shfl_xor_sync(0xffffffffu, besti[j], 16);
                    if (od < bestd[j] || (od == bestd[j] && oi < besti[j])) {
                        bestd[j] = od; besti[j] = oi;
                    }
                }
                const int w = tid >> 5;
                if ((tid & 16) == 0) {
#pragma unroll
                    for (int j = 0; j < 8; ++j) {
                        sm->red_d[w][p0 + j] = bestd[j];
                        sm->red_i[w][p0 + j] = besti[j];
                    }
                }
                __syncthreads();
                if (tid < TM) {
                    float bd = sm->red_d[0][tid];
                    int   bi = sm->red_i[0][tid];
#pragma unroll
                    for (int w2 = 1; w2 < 8; ++w2) {
                        float d2 = sm->red_d[w2][tid];
                        int   i2 = sm->red_i[w2][tid];
                        if (d2 < bd || (d2 == bd && i2 < bi)) { bd = d2; bi = i2; }
                    }
                    // dist strictly > 0 -> float bits are order-preserving
                    unsigned long long pk =
                        ((unsigned long long)__float_as_uint(bd) << 32) | (unsigned)bi;
                    atomicMax(&g_best[cur_tile * TM + tid], ~pk);
                }
                __threadfence();
                if (tid == 0)
                    sm->flag = (atomicAdd(&g_done[cur_tile], seg_chunks)
                                + seg_chunks == 8);
                __syncthreads();

                if (sm->flag) {
                    // ============ tile epilogue (z_s still resident) =========
                    __threadfence();
                    for (int i = tid; i < KCODES; i += 256) sm->cnt_s[i] = 0;
                    __syncthreads();
                    if (tid < TM) {
                        unsigned long long raw =
                            *((volatile unsigned long long*)&g_best[cur_tile * TM + tid]);
                        int bi = (int)(unsigned)((~raw) & 0xFFFFFFFFull);
                        sm->idx_s[tid] = bi;
                        out[OFS_IDX + cur_tile * TM + tid] = (float)bi;
                        atomicAdd(&sm->cnt_s[bi], 1);
                    }
                    __syncthreads();
                    for (int i = tid; i < KCODES; i += 256) {
                        int c = sm->cnt_s[i];
                        if (c) atomicAdd(&g_counts[i], c);
                    }
                    {   // gather z_q, z_q_st (reference two roundings), SSE
                        int p = tid >> 1, h = tid & 1;
                        int ci = sm->idx_s[p];
                        const float4* crow = reinterpret_cast<const float4*>(
                                                 cb + (size_t)ci * D_DIM) + h * 8;
                        float ssel = 0.f;
#pragma unroll
                        for (int i = 0; i < 8; ++i) {
                            float4 v = crow[i];
                            int d0 = h * 32 + i * 4;
                            float vv[4] = {v.x, v.y, v.z, v.w};
#pragma unroll
                            for (int cc = 0; cc < 4; ++cc) {
                                int d = d0 + cc;
                                float zev  = sm->z_s[d][p];
                                float diff = vv[cc] - zev;       // fl(z_q - z_e)
                                ssel = fmaf(diff, diff, ssel);
                                sm->e_s[d][p] = zev + diff;      // fl(z_e + diff)
                            }
                        }
#pragma unroll
                        for (int o = 16; o; o >>= 1)
                            ssel += __shfl_xor_sync(0xffffffffu, ssel, o);
                        if ((tid & 31) == 0) atomicAdd(&g_sse, ssel);
                    }
                    __syncthreads();
                    {   // coalesced z_q_st store
                        float* zo = out + (size_t)b * D_DIM * HW + hw0;
                        for (int f = tid; f < D_DIM * TM; f += 256) {
                            int d = f >> 7, p = f & 127;
                            zo[d * HW + p] = sm->e_s[d][p];
                        }
                    }
                    __threadfence();
                    if (tid == 0)
                        sm->flag2 = (atomicAdd(&g_tiles_done, 1) == NPT - 1);
                    __syncthreads();

                    if (sm->flag2) {
                        // ============ finalize + state reset =================
                        __threadfence();
                        float hpart = 0.f;
                        for (int i = tid; i < KCODES; i += 256) {
                            int c = *((volatile int*)&g_counts[i]);
                            float u = (float)c / 32768.0f;
                            out[OFS_USAGE + i] = u;
                            hpart += u * logf(u + 1e-10f);
                        }
#pragma unroll
                        for (int o = 16; o; o >>= 1)
                            hpart += __shfl_xor_sync(0xffffffffu, hpart, o);
                        if ((tid & 31) == 0) sm->red_d[0][tid >> 5] = hpart;
                        __syncthreads();
                        if (tid == 0) {
                            float H = 0.f;
#pragma unroll
                            for (int w2 = 0; w2 < 8; ++w2) H += sm->red_d[0][w2];
                            out[OFS_PPL] = expf(-H);
                            float msse = *((volatile float*)&g_sse);
                            float m = msse / 2097152.0f;
                            out[OFS_LOSS] = m + 0.25f * m;
                        }
                        __syncthreads();
                        // reset module state for next graph replay
                        for (int i = tid; i < KCODES; i += 256) g_counts[i] = 0;
                        for (int i = tid; i < NPT; i += 256)    g_done[i] = 0;
                        for (int i = tid; i < NPT * TM; i += 256) g_best[i] = 0ull;
                        if (tid == 0) { g_sse = 0.f; g_tiles_done = 0; }
                    }
                }
                __syncthreads();   // epilogue done before z_s is overwritten
            }
            if (tile < 0) break;

            // ================= load new tile ================================
            cur_tile  = tile;
            seg_chunks = 0;
            b   = tile >> 3;
            hw0 = (tile & 7) * TM;
            const float* zbase = ze + (size_t)b * D_DIM * HW + hw0;
            for (int f = tid; f < D_DIM * TM; f += 256) {
                int d = f >> 7, p = f & 127;
                sm->z_s[d][p] = zbase[d * HW + p];
            }
            __syncthreads();
            if (tid < TM) {                          // reference rounding
                float s = 0.f;
#pragma unroll
                for (int d = 0; d < D_DIM; ++d) {
                    float v = sm->z_s[d][tid];
                    s = fmaf(v, v, s);
                }
                sm->z2_s[tid] = s;
            }
            __syncthreads();
#pragma unroll
            for (int j = 0; j < 8; ++j) z2r[j] = sm->z2_s[p0 + j];
#pragma unroll
            for (int j = 0; j < 8; ++j) { bestd[j] = 3.4e38f; besti[j] = 0; }
        }

        // ==================== process one chunk =============================
        const int kb = (q & 7) * KC;

        {   // stage codebook chunk transposed [d][k] (conflict-free STS)
            const float4* src = reinterpret_cast<const float4*>(
                                    cb + (size_t)(kb + k_st) * D_DIM) + h_st * 8;
#pragma unroll
            for (int i = 0; i < 8; ++i) {
                float4 v = src[i];
                int d0 = h_st * 32 + i * 4;
                sm->e_s[d0 + 0][k_st] = v.x;
                sm->e_s[d0 + 1][k_st] = v.y;
                sm->e_s[d0 + 2][k_st] = v.z;
                sm->e_s[d0 + 3][k_st] = v.w;
            }
        }
        __syncthreads();
        if (tid < KC) {                              // inline e2, reference order
            float s = 0.f;
#pragma unroll
            for (int d = 0; d < D_DIM; ++d) {
                float v = sm->e_s[d][tid];
                s = fmaf(v, v, s);
            }
            sm->e2c[tid] = s;
        }
        __syncthreads();

        unsigned long long acc[8][4];
#pragma unroll
        for (int j = 0; j < 8; ++j)
#pragma unroll
            for (int kk = 0; kk < 4; ++kk) acc[j][kk] = 0ull;

#pragma unroll 16
        for (int d = 0; d < D_DIM; ++d) {
            ulonglong2 eA = *reinterpret_cast<const ulonglong2*>(&sm->e_s[d][kloc0]);
            ulonglong2 eB = *reinterpret_cast<const ulonglong2*>(&sm->e_s[d][kloc0 + 4]);
            float4 za = *reinterpret_cast<const float4*>(&sm->z_s[d][p0]);
            float4 zb = *reinterpret_cast<const float4*>(&sm->z_s[d][p0 + 4]);
            float zr[8] = {za.x, za.y, za.z, za.w, zb.x, zb.y, zb.z, zb.w};
#pragma unroll
            for (int j = 0; j < 8; ++j) {
                unsigned long long zz = pack2(zr[j], zr[j]);
                fma2(acc[j][0], zz, eA.x);
                fma2(acc[j][1], zz, eA.y);
                fma2(acc[j][2], zz, eB.x);
                fma2(acc[j][3], zz, eB.y);
            }
        }

        float e2r[8];
#pragma unroll
        for (int kk = 0; kk < 8; ++kk) e2r[kk] = sm->e2c[kloc0 + kk];
#pragma unroll
        for (int j = 0; j < 8; ++j) {
            float a = z2r[j];
#pragma unroll
            for (int kk = 0; kk < 4; ++kk) {
                float2 s = unpack2(acc[j][kk]);
                float d0 = fmaf(-2.f, s.x, a + e2r[kk * 2]);
                float d1 = fmaf(-2.f, s.y, a + e2r[kk * 2 + 1]);
                int k0 = kb + kloc0 + kk * 2;
                if (d0 < bestd[j]) { bestd[j] = d0; besti[j] = k0; }
                if (d1 < bestd[j]) { bestd[j] = d1; besti[j] = k0 + 1; }
            }
        }
        ++seg_chunks;
        __syncthreads();   // all reads of e_s done before next stage/epilogue
    }
}

// ---------------------------------------------------------------------------
extern "C" void kernel_launch(void* const* d_in, const int* in_sizes, int n_in,
                              void* d_out, int out_size) {
    const float* a0 = (const float*)d_in[0];
    const float* a1 = (const float*)d_in[1];
    const float* ze = a0;
    const float* cb = a1;
    if (n_in >= 2 && in_sizes[0] == KCODES * D_DIM) { ze = a1; cb = a0; }
    float* out = (float*)d_out;

    static_assert(sizeof(Sm) < 100 * 1024, "smem too big");
    cudaFuncSetAttribute(vq_all, cudaFuncAttributeMaxDynamicSharedMemorySize,
                         (int)sizeof(Sm));
    vq_all<<<NCTA, 256, sizeof(Sm)>>>(ze, cb, out);
}